// round 15
// baseline (speedup 1.0000x reference)
#include <cuda_runtime.h>
#include <cuda_fp16.h>
#include <math.h>
#include <stdint.h>

#define B_SZ  2
#define T_SZ  2048
#define DEMB  1024
#define NH    16
#define DH    64
#define NG    4
#define FQKV  1536
#define ROPE_N 32

#define QSCALE 0.18033688f   // 0.125 * log2(e)

// -------------------- scratch ----------------------------------------------
__device__ __half g_xh   [(size_t)B_SZ * T_SZ * DEMB];
__device__ __half g_wqkv [(size_t)FQKV * DEMB];
__device__ __half g_wout [(size_t)DEMB * DEMB];
__device__ __half g_qp   [(size_t)B_SZ * NH * T_SZ * DH];
__device__ __half g_kp   [(size_t)B_SZ * NG * T_SZ * DH];
__device__ __half g_vt   [(size_t)B_SZ * NG * DH * T_SZ];
__device__ __half g_yh   [(size_t)B_SZ * T_SZ * DEMB];

// -------------------- helpers ----------------------------------------------
__device__ __forceinline__ uint32_t smem_u32(const void* p) {
    uint32_t a;
    asm("{ .reg .u64 t; cvta.to.shared.u64 t, %1; cvt.u32.u64 %0, t; }"
        : "=r"(a) : "l"(p));
    return a;
}
__device__ __forceinline__ void cp_async16(uint32_t dst, const void* src) {
    asm volatile("cp.async.cg.shared.global [%0], [%1], 16;"
                 :: "r"(dst), "l"(src) : "memory");
}
__device__ __forceinline__ void cp_commit() {
    asm volatile("cp.async.commit_group;" ::: "memory");
}
__device__ __forceinline__ void cp_wait1() {
    asm volatile("cp.async.wait_group 1;" ::: "memory");
}
__device__ __forceinline__ void cp_wait0() {
    asm volatile("cp.async.wait_group 0;" ::: "memory");
}
__device__ __forceinline__ uint32_t packh2(float a, float b) {
    __half2 h = __floats2half2_rn(a, b);
    return *(uint32_t*)&h;
}
__device__ __forceinline__ uint32_t h2ex2(uint32_t s) {
    uint32_t r;
    asm("ex2.approx.f16x2 %0, %1;" : "=r"(r) : "r"(s));
    return r;
}
__device__ __forceinline__ void mma_f16(float* c, const uint32_t* a,
                                        const uint32_t* b) {
    asm volatile(
        "mma.sync.aligned.m16n8k16.row.col.f32.f16.f16.f32 "
        "{%0,%1,%2,%3}, {%4,%5,%6,%7}, {%8,%9}, {%0,%1,%2,%3};"
        : "+f"(c[0]), "+f"(c[1]), "+f"(c[2]), "+f"(c[3])
        : "r"(a[0]), "r"(a[1]), "r"(a[2]), "r"(a[3]), "r"(b[0]), "r"(b[1]));
}
__device__ __forceinline__ void ldsm_x4(uint32_t& r0, uint32_t& r1,
                                        uint32_t& r2, uint32_t& r3,
                                        uint32_t addr) {
    asm volatile(
        "ldmatrix.sync.aligned.m8n8.x4.shared.b16 {%0,%1,%2,%3}, [%4];"
        : "=r"(r0), "=r"(r1), "=r"(r2), "=r"(r3) : "r"(addr));
}

// ---------------------------------------------------------------------------
// Shared GEMM mainloop skeleton: 3-stage cp.async pipeline, BM=BN=128, BK=64.
// ---------------------------------------------------------------------------
#define GSTRH 72
#define GTILE_H (128 * GSTRH)
#define GSTAGE_H (2 * GTILE_H)
#define GEMM_SMEM (3 * GSTAGE_H * 2)     // 110592 B

#define GEMM_MAINLOOP(A_, B_, K_)                                             \
    const __half* ag0 = (A_) + (size_t)bm * (K_);                             \
    const __half* bg0 = (B_) + (size_t)bn * (K_);                             \
    auto load_tile = [&](int kt, int st) {                                    \
        uint32_t da = smb + st * GSTAGE_H * 2;                                \
        uint32_t db = da + GTILE_H * 2;                                       \
        const __half* ag = ag0 + kt * 64;                                     \
        const __half* bg = bg0 + kt * 64;                                     \
        _Pragma("unroll")                                                     \
        for (int t = 0; t < 4; t++) {                                         \
            int idx = tid + t * 256;                                          \
            int row = idx >> 3;                                               \
            int c   = idx & 7;                                                \
            uint32_t off = (uint32_t)(row * GSTRH + c * 8) * 2;               \
            cp_async16(da + off, ag + (size_t)row * (K_) + c * 8);            \
            cp_async16(db + off, bg + (size_t)row * (K_) + c * 8);            \
        }                                                                     \
    };                                                                        \
    load_tile(0, 0); cp_commit();                                             \
    load_tile(1, 1); cp_commit();                                             \
    int stage = 0, stage2 = 2;                                                \
    for (int kt = 0; kt < NT; kt++) {                                         \
        if (kt + 1 < NT) cp_wait1(); else cp_wait0();                         \
        __syncthreads();                                                      \
        if (kt + 2 < NT) { load_tile(kt + 2, stage2); cp_commit(); }          \
        uint32_t sA = smb + stage * GSTAGE_H * 2;                             \
        uint32_t sB = sA + GTILE_H * 2;                                       \
        uint32_t aAddr = sA + (uint32_t)((wm * 64 + (lid & 15)) * GSTRH       \
                                         + (lid >> 4) * 8) * 2;               \
        uint32_t bAddr = sB + (uint32_t)((wn * 32 + (lid & 7)                 \
                                          + (lid >> 4) * 8) * GSTRH           \
                                         + ((lid >> 3) & 1) * 8) * 2;         \
        _Pragma("unroll")                                                     \
        for (int ks = 0; ks < 4; ks++) {                                      \
            uint32_t af[4][4], bf[4][2];                                      \
            _Pragma("unroll")                                                 \
            for (int ma = 0; ma < 4; ma++)                                    \
                ldsm_x4(af[ma][0], af[ma][1], af[ma][2], af[ma][3],           \
                        aAddr + (uint32_t)(ma * 16 * GSTRH) * 2 + ks * 32);   \
            _Pragma("unroll")                                                 \
            for (int np = 0; np < 2; np++)                                    \
                ldsm_x4(bf[2 * np][0], bf[2 * np][1],                         \
                        bf[2 * np + 1][0], bf[2 * np + 1][1],                 \
                        bAddr + (uint32_t)(np * 16 * GSTRH) * 2 + ks * 32);   \
            _Pragma("unroll")                                                 \
            for (int ma = 0; ma < 4; ma++)                                    \
                _Pragma("unroll")                                             \
                for (int na = 0; na < 4; na++)                                \
                    mma_f16(acc[ma][na], af[ma], bf[na]);                     \
        }                                                                     \
        stage = (stage == 2) ? 0 : stage + 1;                                 \
        stage2 = (stage2 == 2) ? 0 : stage2 + 1;                              \
    }

// ---------------------------------------------------------------------------
// transpose tile helper using caller-provided smem (32x33 floats)
// ---------------------------------------------------------------------------
__device__ __forceinline__ void transpose_tile_dyn(
    const float* __restrict__ src, __half* __restrict__ dst,
    int R, int Ccol, int bx, int by, int tid, float* t)
{
    int tx = tid & 31, ty = tid >> 5;
    int x = bx * 32 + tx;
    #pragma unroll
    for (int i = 0; i < 32; i += 8) {
        int r = by * 32 + ty + i;
        t[(ty + i) * 33 + tx] = src[(size_t)r * Ccol + x];
    }
    __syncthreads();
    int xo = by * 32 + tx;
    #pragma unroll
    for (int i = 0; i < 32; i += 8) {
        int c = bx * 32 + ty + i;
        dst[(size_t)c * R + xo] = __float2half_rn(t[tx * 33 + ty + i]);
    }
}

// ---------------------------------------------------------------------------
// Out-projection GEMM: float output, plain epilogue.
// ---------------------------------------------------------------------------
__global__ __launch_bounds__(256, 2) void gemm_out(
    const __half* __restrict__ A, const __half* __restrict__ Bt,
    float* __restrict__ C, int M, int N, int K)
{
    extern __shared__ __align__(16) char smc[];
    const uint32_t smb = smem_u32(smc);
    const int tid = threadIdx.x;
    const int wid = tid >> 5;
    const int lid = tid & 31;
    const int g   = lid >> 2;
    const int tig = lid & 3;
    const int wm  = wid >> 2;
    const int wn  = wid & 3;
    const int bm  = blockIdx.y * 128;
    const int bn  = blockIdx.x * 128;
    const int NT  = K >> 6;

    float acc[4][4][4] = {};
    GEMM_MAINLOOP(A, Bt, K)

    #pragma unroll
    for (int ma = 0; ma < 4; ma++) {
        int row0 = bm + wm * 64 + ma * 16 + g;
        #pragma unroll
        for (int na = 0; na < 4; na++) {
            int col = bn + wn * 32 + na * 8 + 2 * tig;
            *(float2*)&C[(size_t)row0 * N + col] =
                make_float2(acc[ma][na][0], acc[ma][na][1]);
            *(float2*)&C[(size_t)(row0 + 8) * N + col] =
                make_float2(acc[ma][na][2], acc[ma][na][3]);
        }
    }
}

// ---------------------------------------------------------------------------
// QKV GEMM with fused rope + scale + pack epilogue; V staged via smem.
// Extra grid blocks (by >= 32) transpose Wout -> wo (hidden under the GEMM).
// ---------------------------------------------------------------------------
#define VSTG 136
#define GQ_YB 32
#define WO_TILES 1024
#define GQ_EXTRA_Y ((WO_TILES + 11) / 12)   // 86

__global__ __launch_bounds__(256, 2) void gemm_qkv(
    const __half* __restrict__ A, const __half* __restrict__ Bt,
    const float* __restrict__ cosb, const float* __restrict__ sinb,
    __half* __restrict__ qp, __half* __restrict__ kp, __half* __restrict__ vt,
    const float* __restrict__ Wout, __half* __restrict__ wo)
{
    extern __shared__ __align__(16) char smc[];
    const int tid = threadIdx.x;

    if (blockIdx.y >= GQ_YB) {
        int bb = (blockIdx.y - GQ_YB) * 12 + blockIdx.x;
        if (bb < WO_TILES)
            transpose_tile_dyn(Wout, wo, DEMB, DEMB, bb % 32, bb / 32, tid,
                               (float*)smc);
        return;
    }

    const uint32_t smb = smem_u32(smc);
    const int wid = tid >> 5;
    const int lid = tid & 31;
    const int g   = lid >> 2;
    const int tig = lid & 3;
    const int wm  = wid >> 2;
    const int wn  = wid & 3;
    const int bm  = blockIdx.y * 128;
    const int bn  = blockIdx.x * 128;
    const int NT  = DEMB >> 6;   // 16

    float acc[4][4][4] = {};
    GEMM_MAINLOOP(A, Bt, DEMB)

    // ---- fused epilogue ----
    const int colbase = bn + wn * 32;
    const int gr    = colbase / 384;
    const int rem   = colbase % 384;
    const int slot  = rem / 64;              // 0-3 q, 4 k, 5 v
    const int dbase = rem % 64;
    const bool do_rope = (dbase == 0) && (slot != 5);

    __half* vsm = (__half*)smc + wn * 32 * VSTG;

    __syncthreads();   // mainloop smem dead; reuse for V staging

    #pragma unroll
    for (int ma = 0; ma < 4; ma++)
        #pragma unroll
        for (int hr = 0; hr < 2; hr++) {
            int row = bm + wm * 64 + ma * 16 + hr * 8 + g;
            int t  = row & (T_SZ - 1);
            int bb = row >> 11;
            int rl = wm * 64 + ma * 16 + hr * 8 + g;
            float v8[8];
            #pragma unroll
            for (int na = 0; na < 4; na++) {
                v8[2 * na]     = acc[ma][na][2 * hr];
                v8[2 * na + 1] = acc[ma][na][2 * hr + 1];
            }
            if (do_rope) {
                float r8[8];
                #pragma unroll
                for (int i = 0; i < 8; i++) {
                    int d = (i >> 1) * 8 + 2 * tig + (i & 1);
                    float rot = (i < 4) ? -v8[i + 4] : v8[i - 4];
                    r8[i] = v8[i] * cosb[t * ROPE_N + d]
                          + rot   * sinb[t * ROPE_N + d];
                }
                #pragma unroll
                for (int i = 0; i < 8; i++) v8[i] = r8[i];
            }
            if (slot < 4) {
                int hh = gr * 4 + slot;
                __half* dst = qp + (((size_t)bb * NH + hh) * T_SZ + t) * DH
                            + dbase + 2 * tig;
                #pragma unroll
                for (int na = 0; na < 4; na++)
                    *(__half2*)(dst + na * 8) =
                        __floats2half2_rn(v8[2 * na] * QSCALE,
                                          v8[2 * na + 1] * QSCALE);
            } else if (slot == 4) {
                __half* dst = kp + (((size_t)bb * NG + gr) * T_SZ + t) * DH
                            + dbase + 2 * tig;
                #pragma unroll
                for (int na = 0; na < 4; na++)
                    *(__half2*)(dst + na * 8) =
                        __floats2half2_rn(v8[2 * na], v8[2 * na + 1]);
            } else {
                #pragma unroll
                for (int i = 0; i < 8; i++) {
                    int dl = (i >> 1) * 8 + 2 * tig + (i & 1);
                    vsm[dl * VSTG + rl] = __float2half_rn(v8[i]);
                }
            }
        }

    __syncthreads();

    if (slot == 5) {
        int pid = wm * 32 + lid;
        int t0  = bm & (T_SZ - 1);
        int bb  = bm >> 11;
        __half* vrow = vt + ((size_t)(bb * NG + gr) * DH + dbase) * T_SZ
                     + t0 + 2 * pid;
        #pragma unroll
        for (int dl = 0; dl < 32; dl++)
            *(__half2*)(vrow + (size_t)dl * T_SZ) =
                *(__half2*)&vsm[dl * VSTG + 2 * pid];
    }
}

// ---------------------------------------------------------------------------
// Pre-pass: x->half (float4) | Wqkv^T->half
// ---------------------------------------------------------------------------
#define PREP_X_BLOCKS  1024
#define PREP_WQ_BLOCKS 1536
#define PREP_BLOCKS (PREP_X_BLOCKS + PREP_WQ_BLOCKS)

__global__ __launch_bounds__(256) void prep(
    const float* __restrict__ x, const float* __restrict__ Wqkv,
    __half2* __restrict__ xh, __half* __restrict__ wq)
{
    __shared__ float tbuf[32 * 33];
    int blk = blockIdx.x;
    int tid = threadIdx.x;
    if (blk < PREP_X_BLOCKS) {
        const float4* xs = (const float4*)x;
        int base = blk * 1024 + tid;
        #pragma unroll
        for (int i = 0; i < 4; i++) {
            int idx = base + i * 256;
            float4 v = xs[idx];
            xh[2 * idx]     = __floats2half2_rn(v.x, v.y);
            xh[2 * idx + 1] = __floats2half2_rn(v.z, v.w);
        }
    } else {
        int b = blk - PREP_X_BLOCKS;
        transpose_tile_dyn(Wqkv, wq, DEMB, FQKV, b % 48, b / 48, tid, tbuf);
    }
}

// ---------------------------------------------------------------------------
// FA2-style fp16 flash attention: P register-resident, f16x2 ex2 softmax,
// ones-column MMA row sums. K triple-buffered (reusing Q's buffer after the
// qf hoist), V double-buffered: ONE wait + ONE sync per iteration.
// Commit order per iter: V_{j+1} then K_{j+2}, so wait_group(1) leaves exactly
// K_{j+1} in flight and guarantees K_j + V_j complete.
// ---------------------------------------------------------------------------
#define QSTRH 72
#define KSTRH 72
#define VSTRH 136
#define AT_KB0 0
#define AT_KB(i) (AT_KB0 + (i) * 128 * KSTRH)
#define AT_V0 (AT_KB0 + 3 * 128 * KSTRH)
#define AT_V1 (AT_V0 + 64 * VSTRH)
#define AT_END (AT_V1 + 64 * VSTRH)
#define ATTN_SMEM_BYTES (AT_END * 2)     // 90112

__global__ __launch_bounds__(256, 2) void attn_mma(
    const __half* __restrict__ qp, const __half* __restrict__ kp,
    const __half* __restrict__ vt, __half* __restrict__ y)
{
    extern __shared__ __align__(16) char smc[];
    const uint32_t smb = smem_u32(smc);

    const int tid = threadIdx.x;
    const int wid = tid >> 5;
    const int lid = tid & 31;
    const int g   = lid >> 2;
    const int tig = lid & 3;

    const int h = blockIdx.y, b = blockIdx.z;
    const int gr = h >> 2;
    const int qbase = blockIdx.x * 128;

    const __half* qrow = qp + (((size_t)b * NH + h) * T_SZ + qbase) * DH;
    const __half* kb   = kp + ((size_t)b * NG + gr) * T_SZ * DH;
    const __half* vb   = vt + ((size_t)b * NG + gr) * DH * T_SZ;

    auto load_q = [&]() {   // into K-buffer 0 (reused for K after hoist)
        #pragma unroll
        for (int t = 0; t < 4; t++) {
            int idx = tid + t * 256;
            int r = idx >> 3, c = idx & 7;
            cp_async16(smb + (uint32_t)(AT_KB0 + r * QSTRH + c * 8) * 2,
                       qrow + (size_t)r * DH + c * 8);
        }
    };
    auto load_k = [&](int j) {            // K_j -> buffer (j+1)%3
        uint32_t dst = smb + (uint32_t)AT_KB((j + 1) % 3) * 2;
        const __half* src = kb + (size_t)(j * 128) * DH;
        #pragma unroll
        for (int t = 0; t < 4; t++) {
            int idx = tid + t * 256;
            int r = idx >> 3, c = idx & 7;
            cp_async16(dst + (uint32_t)(r * KSTRH + c * 8) * 2,
                       src + (size_t)r * DH + c * 8);
        }
    };
    auto load_v = [&](int j) {            // V_j -> buffer j&1
        uint32_t dst = smb + (uint32_t)((j & 1) ? AT_V1 : AT_V0) * 2;
        const __half* src = vb + j * 128;
        #pragma unroll
        for (int t = 0; t < 4; t++) {
            int idx = tid + t * 256;
            int d = idx >> 4, c = idx & 15;
            cp_async16(dst + (uint32_t)(d * VSTRH + c * 8) * 2,
                       src + (size_t)d * T_SZ + c * 8);
        }
    };

    // prologue: Q(G0) K0(G1) V0(G2) K1(G3)
    load_q();   cp_commit();
    load_k(0);  cp_commit();
    load_v(0);  cp_commit();
    load_k(1);  cp_commit();

    cp_wait1();        // Q, K0, V0 complete; K1 in flight
    __syncthreads();

    // hoist Q fragments from buffer 0
    uint32_t qf[4][4];
    {
        uint32_t qAddr = smb + (uint32_t)(AT_KB0
                       + (wid * 16 + (lid & 15)) * QSTRH
                       + (lid >> 4) * 8) * 2;
        #pragma unroll
        for (int ks = 0; ks < 4; ks++)
            ldsm_x4(qf[ks][0], qf[ks][1], qf[ks][2], qf[ks][3],
                    qAddr + ks * 32);
    }
    __syncthreads();   // buffer 0 reads done; safe for K2 writes

    float o[8][4] = {};
    float lacc[4] = {};
    const uint32_t onesb[2] = {0x3C003C00u, 0x3C003C00u};

    const uint32_t kRowOff = (uint32_t)(((lid & 7) + ((lid >> 4) << 3)) * KSTRH
                                        + ((lid >> 3) & 1) * 8) * 2;
    const uint32_t vRowOff = (uint32_t)(((lid & 7) + ((lid >> 4) << 3)) * VSTRH
                                        + ((lid >> 3) & 1) * 8) * 2;

    const int NJ = T_SZ / 128;   // 16
    for (int j = 0; j < NJ; j++) {
        if (j > 0) {
            // need K_j and V_j done; only K_{j+1} may remain in flight
            if (j + 1 < NJ) cp_wait1(); else cp_wait0();
            __syncthreads();
        }
        // prefetch: V first, then K (commit order matters for wait_group 1)
        if (j + 1 < NJ) { load_v(j + 1); cp_commit(); }
        if (j + 2 < NJ) { load_k(j + 2); cp_commit(); }

        const uint32_t kBase = smb + (uint32_t)AT_KB((j + 1) % 3) * 2
                             + kRowOff;
        const uint32_t vBase = smb + (uint32_t)((j & 1) ? AT_V1 : AT_V0) * 2
                             + vRowOff;

        // ---- QK + f16x2 exp + pack (registers only) ----
        uint32_t pf[2][4][4];
        #pragma unroll
        for (int hf = 0; hf < 2; hf++) {
            float sc[8][4] = {};
            #pragma unroll
            for (int ks = 0; ks < 4; ks++) {
                uint32_t bf[8][2];
                #pragma unroll
                for (int np = 0; np < 4; np++)
                    ldsm_x4(bf[2 * np][0], bf[2 * np][1],
                            bf[2 * np + 1][0], bf[2 * np + 1][1],
                            kBase + (uint32_t)((hf * 64 + np * 16) * KSTRH) * 2
                                  + ks * 32);
                #pragma unroll
                for (int nt = 0; nt < 8; nt++)
                    mma_f16(sc[nt], qf[ks], bf[nt]);
            }
            #pragma unroll
            for (int kk = 0; kk < 4; kk++) {
                int n0 = 2 * kk, n1 = n0 + 1;
                pf[hf][kk][0] = h2ex2(packh2(sc[n0][0], sc[n0][1]));
                pf[hf][kk][1] = h2ex2(packh2(sc[n0][2], sc[n0][3]));
                pf[hf][kk][2] = h2ex2(packh2(sc[n1][0], sc[n1][1]));
                pf[hf][kk][3] = h2ex2(packh2(sc[n1][2], sc[n1][3]));
            }
        }

        // ---- O += P @ V ; l += P @ 1 (V_j guaranteed resident) ----
        #pragma unroll
        for (int kk = 0; kk < 8; kk++) {
            const uint32_t* pa = pf[kk >> 2][kk & 3];
            uint32_t vf[8][2];
            #pragma unroll
            for (int nd = 0; nd < 4; nd++)
                ldsm_x4(vf[2 * nd][0], vf[2 * nd][1],
                        vf[2 * nd + 1][0], vf[2 * nd + 1][1],
                        vBase + (uint32_t)(nd * 16 * VSTRH) * 2 + kk * 32);
            #pragma unroll
            for (int nt = 0; nt < 8; nt++)
                mma_f16(o[nt], pa, vf[nt]);
            mma_f16(lacc, pa, onesb);
        }
    }

    float li0 = 1.0f / lacc[0];
    float li1 = 1.0f / lacc[2];

    size_t yrow0 = ((size_t)b * T_SZ + qbase + wid * 16 + g) * DEMB + h * DH;
    size_t yrow1 = yrow0 + 8 * DEMB;
    #pragma unroll
    for (int nt = 0; nt < 8; nt++) {
        int col = nt * 8 + 2 * tig;
        *(__half2*)&y[yrow0 + col] =
            __floats2half2_rn(o[nt][0] * li0, o[nt][1] * li0);
        *(__half2*)&y[yrow1 + col] =
            __floats2half2_rn(o[nt][2] * li1, o[nt][3] * li1);
    }
}

// ---------------------------------------------------------------------------
extern "C" void kernel_launch(void* const* d_in, const int* in_sizes, int n_in,
                              void* d_out, int out_size)
{
    const float* x    = (const float*)d_in[0];
    const float* cosb = (const float*)d_in[1];
    const float* sinb = (const float*)d_in[2];
    const float* Wqkv = (const float*)d_in[4];
    const float* Wout = (const float*)d_in[5];
    float* out = (float*)d_out;

    __half *xh_p, *wq_p, *wo_p, *qp_p, *kp_p, *vt_p, *yh_p;
    cudaGetSymbolAddress((void**)&xh_p, g_xh);
    cudaGetSymbolAddress((void**)&wq_p, g_wqkv);
    cudaGetSymbolAddress((void**)&wo_p, g_wout);
    cudaGetSymbolAddress((void**)&qp_p, g_qp);
    cudaGetSymbolAddress((void**)&kp_p, g_kp);
    cudaGetSymbolAddress((void**)&vt_p, g_vt);
    cudaGetSymbolAddress((void**)&yh_p, g_yh);

    cudaFuncSetAttribute(gemm_qkv,
                         cudaFuncAttributeMaxDynamicSharedMemorySize, GEMM_SMEM);
    cudaFuncSetAttribute(gemm_out,
                         cudaFuncAttributeMaxDynamicSharedMemorySize, GEMM_SMEM);
    cudaFuncSetAttribute(attn_mma,
                         cudaFuncAttributeMaxDynamicSharedMemorySize,
                         ATTN_SMEM_BYTES);

    const int M = B_SZ * T_SZ;

    // pre-pass: x f2h (float4) + Wqkv transpose
    prep<<<PREP_BLOCKS, 256>>>(x, Wqkv, (__half2*)xh_p, wq_p);

    // fused: qkv GEMM (+rope/pack/V) with Wout transpose hidden in extra blocks
    gemm_qkv<<<dim3(FQKV / 128, GQ_YB + GQ_EXTRA_Y), 256, GEMM_SMEM>>>(
        xh_p, wq_p, cosb, sinb, qp_p, kp_p, vt_p, Wout, wo_p);

    // attention -> yh
    {
        dim3 grid(T_SZ / 128, NH, B_SZ);
        attn_mma<<<grid, 256, ATTN_SMEM_BYTES>>>(qp_p, kp_p, vt_p, yh_p);
    }

    // out = y @ Wout
    gemm_out<<<dim3(DEMB / 128, M / 128), 256, GEMM_SMEM>>>(
        yh_p, wo_p, out, M, DEMB, DEMB);
}

// round 16
// speedup vs baseline: 1.0014x; 1.0014x over previous
#include <cuda_runtime.h>
#include <cuda_fp16.h>
#include <math.h>
#include <stdint.h>

#define B_SZ  2
#define T_SZ  2048
#define DEMB  1024
#define NH    16
#define DH    64
#define NG    4
#define FQKV  1536
#define ROPE_N 32

#define QSCALE 0.18033688f   // 0.125 * log2(e)

// -------------------- scratch ----------------------------------------------
__device__ __half g_xh   [(size_t)B_SZ * T_SZ * DEMB];
__device__ __half g_wqkv [(size_t)FQKV * DEMB];
__device__ __half g_wout [(size_t)DEMB * DEMB];
__device__ __half g_qp   [(size_t)B_SZ * NH * T_SZ * DH];
__device__ __half g_kp   [(size_t)B_SZ * NG * T_SZ * DH];
__device__ __half g_vt   [(size_t)B_SZ * NG * DH * T_SZ];
__device__ __half g_yh   [(size_t)B_SZ * T_SZ * DEMB];

// -------------------- helpers ----------------------------------------------
__device__ __forceinline__ uint32_t smem_u32(const void* p) {
    uint32_t a;
    asm("{ .reg .u64 t; cvta.to.shared.u64 t, %1; cvt.u32.u64 %0, t; }"
        : "=r"(a) : "l"(p));
    return a;
}
__device__ __forceinline__ void cp_async16(uint32_t dst, const void* src) {
    asm volatile("cp.async.cg.shared.global [%0], [%1], 16;"
                 :: "r"(dst), "l"(src) : "memory");
}
__device__ __forceinline__ void cp_commit() {
    asm volatile("cp.async.commit_group;" ::: "memory");
}
__device__ __forceinline__ void cp_wait1() {
    asm volatile("cp.async.wait_group 1;" ::: "memory");
}
__device__ __forceinline__ void cp_wait0() {
    asm volatile("cp.async.wait_group 0;" ::: "memory");
}
__device__ __forceinline__ uint32_t packh2(float a, float b) {
    __half2 h = __floats2half2_rn(a, b);
    return *(uint32_t*)&h;
}
__device__ __forceinline__ uint32_t h2ex2(uint32_t s) {
    uint32_t r;
    asm("ex2.approx.f16x2 %0, %1;" : "=r"(r) : "r"(s));
    return r;
}
__device__ __forceinline__ void mma_f16(float* c, const uint32_t* a,
                                        const uint32_t* b) {
    asm volatile(
        "mma.sync.aligned.m16n8k16.row.col.f32.f16.f16.f32 "
        "{%0,%1,%2,%3}, {%4,%5,%6,%7}, {%8,%9}, {%0,%1,%2,%3};"
        : "+f"(c[0]), "+f"(c[1]), "+f"(c[2]), "+f"(c[3])
        : "r"(a[0]), "r"(a[1]), "r"(a[2]), "r"(a[3]), "r"(b[0]), "r"(b[1]));
}
__device__ __forceinline__ void ldsm_x4(uint32_t& r0, uint32_t& r1,
                                        uint32_t& r2, uint32_t& r3,
                                        uint32_t addr) {
    asm volatile(
        "ldmatrix.sync.aligned.m8n8.x4.shared.b16 {%0,%1,%2,%3}, [%4];"
        : "=r"(r0), "=r"(r1), "=r"(r2), "=r"(r3) : "r"(addr));
}

// ---------------------------------------------------------------------------
// 128x128 GEMM mainloop skeleton (used by gemm_qkv): 3-stage cp.async, BK=64.
// ---------------------------------------------------------------------------
#define GSTRH 72
#define GTILE_H (128 * GSTRH)
#define GSTAGE_H (2 * GTILE_H)
#define GEMM_SMEM (3 * GSTAGE_H * 2)     // 110592 B

#define GEMM_MAINLOOP(A_, B_, K_)                                             \
    const __half* ag0 = (A_) + (size_t)bm * (K_);                             \
    const __half* bg0 = (B_) + (size_t)bn * (K_);                             \
    auto load_tile = [&](int kt, int st) {                                    \
        uint32_t da = smb + st * GSTAGE_H * 2;                                \
        uint32_t db = da + GTILE_H * 2;                                       \
        const __half* ag = ag0 + kt * 64;                                     \
        const __half* bg = bg0 + kt * 64;                                     \
        _Pragma("unroll")                                                     \
        for (int t = 0; t < 4; t++) {                                         \
            int idx = tid + t * 256;                                          \
            int row = idx >> 3;                                               \
            int c   = idx & 7;                                                \
            uint32_t off = (uint32_t)(row * GSTRH + c * 8) * 2;               \
            cp_async16(da + off, ag + (size_t)row * (K_) + c * 8);            \
            cp_async16(db + off, bg + (size_t)row * (K_) + c * 8);            \
        }                                                                     \
    };                                                                        \
    load_tile(0, 0); cp_commit();                                             \
    load_tile(1, 1); cp_commit();                                             \
    int stage = 0, stage2 = 2;                                                \
    for (int kt = 0; kt < NT; kt++) {                                         \
        if (kt + 1 < NT) cp_wait1(); else cp_wait0();                         \
        __syncthreads();                                                      \
        if (kt + 2 < NT) { load_tile(kt + 2, stage2); cp_commit(); }          \
        uint32_t sA = smb + stage * GSTAGE_H * 2;                             \
        uint32_t sB = sA + GTILE_H * 2;                                       \
        uint32_t aAddr = sA + (uint32_t)((wm * 64 + (lid & 15)) * GSTRH       \
                                         + (lid >> 4) * 8) * 2;               \
        uint32_t bAddr = sB + (uint32_t)((wn * 32 + (lid & 7)                 \
                                          + (lid >> 4) * 8) * GSTRH           \
                                         + ((lid >> 3) & 1) * 8) * 2;         \
        _Pragma("unroll")                                                     \
        for (int ks = 0; ks < 4; ks++) {                                      \
            uint32_t af[4][4], bf[4][2];                                      \
            _Pragma("unroll")                                                 \
            for (int ma = 0; ma < 4; ma++)                                    \
                ldsm_x4(af[ma][0], af[ma][1], af[ma][2], af[ma][3],           \
                        aAddr + (uint32_t)(ma * 16 * GSTRH) * 2 + ks * 32);   \
            _Pragma("unroll")                                                 \
            for (int np = 0; np < 2; np++)                                    \
                ldsm_x4(bf[2 * np][0], bf[2 * np][1],                         \
                        bf[2 * np + 1][0], bf[2 * np + 1][1],                 \
                        bAddr + (uint32_t)(np * 16 * GSTRH) * 2 + ks * 32);   \
            _Pragma("unroll")                                                 \
            for (int ma = 0; ma < 4; ma++)                                    \
                _Pragma("unroll")                                             \
                for (int na = 0; na < 4; na++)                                \
                    mma_f16(acc[ma][na], af[ma], bf[na]);                     \
        }                                                                     \
        stage = (stage == 2) ? 0 : stage + 1;                                 \
        stage2 = (stage2 == 2) ? 0 : stage2 + 1;                              \
    }

// ---------------------------------------------------------------------------
// transpose tile helper using caller-provided smem (32x33 floats)
// ---------------------------------------------------------------------------
__device__ __forceinline__ void transpose_tile_dyn(
    const float* __restrict__ src, __half* __restrict__ dst,
    int R, int Ccol, int bx, int by, int tid, float* t)
{
    int tx = tid & 31, ty = tid >> 5;
    int x = bx * 32 + tx;
    #pragma unroll
    for (int i = 0; i < 32; i += 8) {
        int r = by * 32 + ty + i;
        t[(ty + i) * 33 + tx] = src[(size_t)r * Ccol + x];
    }
    __syncthreads();
    int xo = by * 32 + tx;
    #pragma unroll
    for (int i = 0; i < 32; i += 8) {
        int c = bx * 32 + ty + i;
        dst[(size_t)c * R + xo] = __float2half_rn(t[tx * 33 + ty + i]);
    }
}

// ---------------------------------------------------------------------------
// Big-tile out-projection GEMM: BM=128, BN=256, BK=64, warp tile 64x64,
// 1 CTA/SM, 3-stage. Halves per-FLOP smem fragment traffic vs 128x128.
// ---------------------------------------------------------------------------
#define BG_ATILE (128 * GSTRH)              // halves
#define BG_BTILE (256 * GSTRH)
#define BG_STAGE (BG_ATILE + BG_BTILE)      // 27648 halves
#define BG_SMEM (3 * BG_STAGE * 2)          // 165888 B

__global__ __launch_bounds__(256, 1) void gemm_big(
    const __half* __restrict__ A, const __half* __restrict__ Bt,
    float* __restrict__ C, int M, int N, int K)
{
    extern __shared__ __align__(16) char smc[];
    const uint32_t smb = smem_u32(smc);
    const int tid = threadIdx.x;
    const int wid = tid >> 5;
    const int lid = tid & 31;
    const int g   = lid >> 2;
    const int tig = lid & 3;
    const int wm  = wid >> 2;      // 0..1 (64-row slab)
    const int wn  = wid & 3;       // 0..3 (64-col slab)
    const int bm  = blockIdx.y * 128;
    const int bn  = blockIdx.x * 256;
    const int NT  = K >> 6;

    const __half* ag0 = A  + (size_t)bm * K;
    const __half* bg0 = Bt + (size_t)bn * K;

    auto load_tile = [&](int kt, int st) {
        uint32_t da = smb + st * BG_STAGE * 2;
        uint32_t db = da + BG_ATILE * 2;
        const __half* ag = ag0 + kt * 64;
        const __half* bg = bg0 + kt * 64;
        #pragma unroll
        for (int t = 0; t < 4; t++) {        // A: 128 rows x 8 chunks
            int idx = tid + t * 256;
            int row = idx >> 3;
            int c   = idx & 7;
            cp_async16(da + (uint32_t)(row * GSTRH + c * 8) * 2,
                       ag + (size_t)row * K + c * 8);
        }
        #pragma unroll
        for (int t = 0; t < 8; t++) {        // B: 256 rows x 8 chunks
            int idx = tid + t * 256;
            int row = idx >> 3;
            int c   = idx & 7;
            cp_async16(db + (uint32_t)(row * GSTRH + c * 8) * 2,
                       bg + (size_t)row * K + c * 8);
        }
    };

    float acc[4][8][4] = {};

    load_tile(0, 0); cp_commit();
    load_tile(1, 1); cp_commit();

    int stage = 0, stage2 = 2;
    for (int kt = 0; kt < NT; kt++) {
        if (kt + 1 < NT) cp_wait1(); else cp_wait0();
        __syncthreads();
        if (kt + 2 < NT) { load_tile(kt + 2, stage2); cp_commit(); }

        uint32_t sA = smb + stage * BG_STAGE * 2;
        uint32_t sB = sA + BG_ATILE * 2;
        uint32_t aAddr = sA + (uint32_t)((wm * 64 + (lid & 15)) * GSTRH
                                         + (lid >> 4) * 8) * 2;
        uint32_t bAddr = sB + (uint32_t)((wn * 64 + (lid & 7)
                                          + ((lid >> 4) << 3)) * GSTRH
                                         + ((lid >> 3) & 1) * 8) * 2;

        #pragma unroll
        for (int ks = 0; ks < 4; ks++) {
            uint32_t af[4][4], bf[8][2];
            #pragma unroll
            for (int ma = 0; ma < 4; ma++)
                ldsm_x4(af[ma][0], af[ma][1], af[ma][2], af[ma][3],
                        aAddr + (uint32_t)(ma * 16 * GSTRH) * 2 + ks * 32);
            #pragma unroll
            for (int np = 0; np < 4; np++)
                ldsm_x4(bf[2 * np][0], bf[2 * np][1],
                        bf[2 * np + 1][0], bf[2 * np + 1][1],
                        bAddr + (uint32_t)(np * 16 * GSTRH) * 2 + ks * 32);
            #pragma unroll
            for (int ma = 0; ma < 4; ma++)
                #pragma unroll
                for (int nt = 0; nt < 8; nt++)
                    mma_f16(acc[ma][nt], af[ma], bf[nt]);
        }
        stage = (stage == 2) ? 0 : stage + 1;
        stage2 = (stage2 == 2) ? 0 : stage2 + 1;
    }

    #pragma unroll
    for (int ma = 0; ma < 4; ma++) {
        int row0 = bm + wm * 64 + ma * 16 + g;
        #pragma unroll
        for (int nt = 0; nt < 8; nt++) {
            int col = bn + wn * 64 + nt * 8 + 2 * tig;
            *(float2*)&C[(size_t)row0 * N + col] =
                make_float2(acc[ma][nt][0], acc[ma][nt][1]);
            *(float2*)&C[(size_t)(row0 + 8) * N + col] =
                make_float2(acc[ma][nt][2], acc[ma][nt][3]);
        }
    }
}

// ---------------------------------------------------------------------------
// QKV GEMM with fused rope + scale + pack epilogue; V staged via smem.
// Extra grid blocks (by >= 32) transpose Wout -> wo (hidden under the GEMM).
// ---------------------------------------------------------------------------
#define VSTG 136
#define GQ_YB 32
#define WO_TILES 1024
#define GQ_EXTRA_Y ((WO_TILES + 11) / 12)   // 86

__global__ __launch_bounds__(256, 2) void gemm_qkv(
    const __half* __restrict__ A, const __half* __restrict__ Bt,
    const float* __restrict__ cosb, const float* __restrict__ sinb,
    __half* __restrict__ qp, __half* __restrict__ kp, __half* __restrict__ vt,
    const float* __restrict__ Wout, __half* __restrict__ wo)
{
    extern __shared__ __align__(16) char smc[];
    const int tid = threadIdx.x;

    if (blockIdx.y >= GQ_YB) {
        int bb = (blockIdx.y - GQ_YB) * 12 + blockIdx.x;
        if (bb < WO_TILES)
            transpose_tile_dyn(Wout, wo, DEMB, DEMB, bb % 32, bb / 32, tid,
                               (float*)smc);
        return;
    }

    const uint32_t smb = smem_u32(smc);
    const int wid = tid >> 5;
    const int lid = tid & 31;
    const int g   = lid >> 2;
    const int tig = lid & 3;
    const int wm  = wid >> 2;
    const int wn  = wid & 3;
    const int bm  = blockIdx.y * 128;
    const int bn  = blockIdx.x * 128;
    const int NT  = DEMB >> 6;   // 16

    float acc[4][4][4] = {};
    GEMM_MAINLOOP(A, Bt, DEMB)

    // ---- fused epilogue ----
    const int colbase = bn + wn * 32;
    const int gr    = colbase / 384;
    const int rem   = colbase % 384;
    const int slot  = rem / 64;              // 0-3 q, 4 k, 5 v
    const int dbase = rem % 64;
    const bool do_rope = (dbase == 0) && (slot != 5);

    __half* vsm = (__half*)smc + wn * 32 * VSTG;

    __syncthreads();   // mainloop smem dead; reuse for V staging

    #pragma unroll
    for (int ma = 0; ma < 4; ma++)
        #pragma unroll
        for (int hr = 0; hr < 2; hr++) {
            int row = bm + wm * 64 + ma * 16 + hr * 8 + g;
            int t  = row & (T_SZ - 1);
            int bb = row >> 11;
            int rl = wm * 64 + ma * 16 + hr * 8 + g;
            float v8[8];
            #pragma unroll
            for (int na = 0; na < 4; na++) {
                v8[2 * na]     = acc[ma][na][2 * hr];
                v8[2 * na + 1] = acc[ma][na][2 * hr + 1];
            }
            if (do_rope) {
                float r8[8];
                #pragma unroll
                for (int i = 0; i < 8; i++) {
                    int d = (i >> 1) * 8 + 2 * tig + (i & 1);
                    float rot = (i < 4) ? -v8[i + 4] : v8[i - 4];
                    r8[i] = v8[i] * cosb[t * ROPE_N + d]
                          + rot   * sinb[t * ROPE_N + d];
                }
                #pragma unroll
                for (int i = 0; i < 8; i++) v8[i] = r8[i];
            }
            if (slot < 4) {
                int hh = gr * 4 + slot;
                __half* dst = qp + (((size_t)bb * NH + hh) * T_SZ + t) * DH
                            + dbase + 2 * tig;
                #pragma unroll
                for (int na = 0; na < 4; na++)
                    *(__half2*)(dst + na * 8) =
                        __floats2half2_rn(v8[2 * na] * QSCALE,
                                          v8[2 * na + 1] * QSCALE);
            } else if (slot == 4) {
                __half* dst = kp + (((size_t)bb * NG + gr) * T_SZ + t) * DH
                            + dbase + 2 * tig;
                #pragma unroll
                for (int na = 0; na < 4; na++)
                    *(__half2*)(dst + na * 8) =
                        __floats2half2_rn(v8[2 * na], v8[2 * na + 1]);
            } else {
                #pragma unroll
                for (int i = 0; i < 8; i++) {
                    int dl = (i >> 1) * 8 + 2 * tig + (i & 1);
                    vsm[dl * VSTG + rl] = __float2half_rn(v8[i]);
                }
            }
        }

    __syncthreads();

    if (slot == 5) {
        int pid = wm * 32 + lid;
        int t0  = bm & (T_SZ - 1);
        int bb  = bm >> 11;
        __half* vrow = vt + ((size_t)(bb * NG + gr) * DH + dbase) * T_SZ
                     + t0 + 2 * pid;
        #pragma unroll
        for (int dl = 0; dl < 32; dl++)
            *(__half2*)(vrow + (size_t)dl * T_SZ) =
                *(__half2*)&vsm[dl * VSTG + 2 * pid];
    }
}

// ---------------------------------------------------------------------------
// Pre-pass: x->half (float4) | Wqkv^T->half
// ---------------------------------------------------------------------------
#define PREP_X_BLOCKS  1024
#define PREP_WQ_BLOCKS 1536
#define PREP_BLOCKS (PREP_X_BLOCKS + PREP_WQ_BLOCKS)

__global__ __launch_bounds__(256) void prep(
    const float* __restrict__ x, const float* __restrict__ Wqkv,
    __half2* __restrict__ xh, __half* __restrict__ wq)
{
    __shared__ float tbuf[32 * 33];
    int blk = blockIdx.x;
    int tid = threadIdx.x;
    if (blk < PREP_X_BLOCKS) {
        const float4* xs = (const float4*)x;
        int base = blk * 1024 + tid;
        #pragma unroll
        for (int i = 0; i < 4; i++) {
            int idx = base + i * 256;
            float4 v = xs[idx];
            xh[2 * idx]     = __floats2half2_rn(v.x, v.y);
            xh[2 * idx + 1] = __floats2half2_rn(v.z, v.w);
        }
    } else {
        int b = blk - PREP_X_BLOCKS;
        transpose_tile_dyn(Wqkv, wq, DEMB, FQKV, b % 48, b / 48, tid, tbuf);
    }
}

// ---------------------------------------------------------------------------
// FA2-style fp16 flash attention (unchanged from R15): P register-resident,
// f16x2 ex2 softmax, ones-column MMA row sums, K triple-buffered, V double-
// buffered, one wait + one sync per iteration, 2 CTAs/SM.
// ---------------------------------------------------------------------------
#define QSTRH 72
#define KSTRH 72
#define VSTRH 136
#define AT_KB0 0
#define AT_KB(i) (AT_KB0 + (i) * 128 * KSTRH)
#define AT_V0 (AT_KB0 + 3 * 128 * KSTRH)
#define AT_V1 (AT_V0 + 64 * VSTRH)
#define AT_END (AT_V1 + 64 * VSTRH)
#define ATTN_SMEM_BYTES (AT_END * 2)     // 90112

__global__ __launch_bounds__(256, 2) void attn_mma(
    const __half* __restrict__ qp, const __half* __restrict__ kp,
    const __half* __restrict__ vt, __half* __restrict__ y)
{
    extern __shared__ __align__(16) char smc[];
    const uint32_t smb = smem_u32(smc);

    const int tid = threadIdx.x;
    const int wid = tid >> 5;
    const int lid = tid & 31;
    const int g   = lid >> 2;
    const int tig = lid & 3;

    const int h = blockIdx.y, b = blockIdx.z;
    const int gr = h >> 2;
    const int qbase = blockIdx.x * 128;

    const __half* qrow = qp + (((size_t)b * NH + h) * T_SZ + qbase) * DH;
    const __half* kb   = kp + ((size_t)b * NG + gr) * T_SZ * DH;
    const __half* vb   = vt + ((size_t)b * NG + gr) * DH * T_SZ;

    auto load_q = [&]() {
        #pragma unroll
        for (int t = 0; t < 4; t++) {
            int idx = tid + t * 256;
            int r = idx >> 3, c = idx & 7;
            cp_async16(smb + (uint32_t)(AT_KB0 + r * QSTRH + c * 8) * 2,
                       qrow + (size_t)r * DH + c * 8);
        }
    };
    auto load_k = [&](int j) {
        uint32_t dst = smb + (uint32_t)AT_KB((j + 1) % 3) * 2;
        const __half* src = kb + (size_t)(j * 128) * DH;
        #pragma unroll
        for (int t = 0; t < 4; t++) {
            int idx = tid + t * 256;
            int r = idx >> 3, c = idx & 7;
            cp_async16(dst + (uint32_t)(r * KSTRH + c * 8) * 2,
                       src + (size_t)r * DH + c * 8);
        }
    };
    auto load_v = [&](int j) {
        uint32_t dst = smb + (uint32_t)((j & 1) ? AT_V1 : AT_V0) * 2;
        const __half* src = vb + j * 128;
        #pragma unroll
        for (int t = 0; t < 4; t++) {
            int idx = tid + t * 256;
            int d = idx >> 4, c = idx & 15;
            cp_async16(dst + (uint32_t)(d * VSTRH + c * 8) * 2,
                       src + (size_t)d * T_SZ + c * 8);
        }
    };

    load_q();   cp_commit();
    load_k(0);  cp_commit();
    load_v(0);  cp_commit();
    load_k(1);  cp_commit();

    cp_wait1();
    __syncthreads();

    uint32_t qf[4][4];
    {
        uint32_t qAddr = smb + (uint32_t)(AT_KB0
                       + (wid * 16 + (lid & 15)) * QSTRH
                       + (lid >> 4) * 8) * 2;
        #pragma unroll
        for (int ks = 0; ks < 4; ks++)
            ldsm_x4(qf[ks][0], qf[ks][1], qf[ks][2], qf[ks][3],
                    qAddr + ks * 32);
    }
    __syncthreads();

    float o[8][4] = {};
    float lacc[4] = {};
    const uint32_t onesb[2] = {0x3C003C00u, 0x3C003C00u};

    const uint32_t kRowOff = (uint32_t)(((lid & 7) + ((lid >> 4) << 3)) * KSTRH
                                        + ((lid >> 3) & 1) * 8) * 2;
    const uint32_t vRowOff = (uint32_t)(((lid & 7) + ((lid >> 4) << 3)) * VSTRH
                                        + ((lid >> 3) & 1) * 8) * 2;

    const int NJ = T_SZ / 128;   // 16
    for (int j = 0; j < NJ; j++) {
        if (j > 0) {
            if (j + 1 < NJ) cp_wait1(); else cp_wait0();
            __syncthreads();
        }
        if (j + 1 < NJ) { load_v(j + 1); cp_commit(); }
        if (j + 2 < NJ) { load_k(j + 2); cp_commit(); }

        const uint32_t kBase = smb + (uint32_t)AT_KB((j + 1) % 3) * 2
                             + kRowOff;
        const uint32_t vBase = smb + (uint32_t)((j & 1) ? AT_V1 : AT_V0) * 2
                             + vRowOff;

        uint32_t pf[2][4][4];
        #pragma unroll
        for (int hf = 0; hf < 2; hf++) {
            float sc[8][4] = {};
            #pragma unroll
            for (int ks = 0; ks < 4; ks++) {
                uint32_t bf[8][2];
                #pragma unroll
                for (int np = 0; np < 4; np++)
                    ldsm_x4(bf[2 * np][0], bf[2 * np][1],
                            bf[2 * np + 1][0], bf[2 * np + 1][1],
                            kBase + (uint32_t)((hf * 64 + np * 16) * KSTRH) * 2
                                  + ks * 32);
                #pragma unroll
                for (int nt = 0; nt < 8; nt++)
                    mma_f16(sc[nt], qf[ks], bf[nt]);
            }
            #pragma unroll
            for (int kk = 0; kk < 4; kk++) {
                int n0 = 2 * kk, n1 = n0 + 1;
                pf[hf][kk][0] = h2ex2(packh2(sc[n0][0], sc[n0][1]));
                pf[hf][kk][1] = h2ex2(packh2(sc[n0][2], sc[n0][3]));
                pf[hf][kk][2] = h2ex2(packh2(sc[n1][0], sc[n1][1]));
                pf[hf][kk][3] = h2ex2(packh2(sc[n1][2], sc[n1][3]));
            }
        }

        #pragma unroll
        for (int kk = 0; kk < 8; kk++) {
            const uint32_t* pa = pf[kk >> 2][kk & 3];
            uint32_t vf[8][2];
            #pragma unroll
            for (int nd = 0; nd < 4; nd++)
                ldsm_x4(vf[2 * nd][0], vf[2 * nd][1],
                        vf[2 * nd + 1][0], vf[2 * nd + 1][1],
                        vBase + (uint32_t)(nd * 16 * VSTRH) * 2 + kk * 32);
            #pragma unroll
            for (int nt = 0; nt < 8; nt++)
                mma_f16(o[nt], pa, vf[nt]);
            mma_f16(lacc, pa, onesb);
        }
    }

    float li0 = 1.0f / lacc[0];
    float li1 = 1.0f / lacc[2];

    size_t yrow0 = ((size_t)b * T_SZ + qbase + wid * 16 + g) * DEMB + h * DH;
    size_t yrow1 = yrow0 + 8 * DEMB;
    #pragma unroll
    for (int nt = 0; nt < 8; nt++) {
        int col = nt * 8 + 2 * tig;
        *(__half2*)&y[yrow0 + col] =
            __floats2half2_rn(o[nt][0] * li0, o[nt][1] * li0);
        *(__half2*)&y[yrow1 + col] =
            __floats2half2_rn(o[nt][2] * li1, o[nt][3] * li1);
    }
}

// ---------------------------------------------------------------------------
extern "C" void kernel_launch(void* const* d_in, const int* in_sizes, int n_in,
                              void* d_out, int out_size)
{
    const float* x    = (const float*)d_in[0];
    const float* cosb = (const float*)d_in[1];
    const float* sinb = (const float*)d_in[2];
    const float* Wqkv = (const float*)d_in[4];
    const float* Wout = (const float*)d_in[5];
    float* out = (float*)d_out;

    __half *xh_p, *wq_p, *wo_p, *qp_p, *kp_p, *vt_p, *yh_p;
    cudaGetSymbolAddress((void**)&xh_p, g_xh);
    cudaGetSymbolAddress((void**)&wq_p, g_wqkv);
    cudaGetSymbolAddress((void**)&wo_p, g_wout);
    cudaGetSymbolAddress((void**)&qp_p, g_qp);
    cudaGetSymbolAddress((void**)&kp_p, g_kp);
    cudaGetSymbolAddress((void**)&vt_p, g_vt);
    cudaGetSymbolAddress((void**)&yh_p, g_yh);

    cudaFuncSetAttribute(gemm_qkv,
                         cudaFuncAttributeMaxDynamicSharedMemorySize, GEMM_SMEM);
    cudaFuncSetAttribute(gemm_big,
                         cudaFuncAttributeMaxDynamicSharedMemorySize, BG_SMEM);
    cudaFuncSetAttribute(attn_mma,
                         cudaFuncAttributeMaxDynamicSharedMemorySize,
                         ATTN_SMEM_BYTES);

    const int M = B_SZ * T_SZ;

    // pre-pass: x f2h (float4) + Wqkv transpose
    prep<<<PREP_BLOCKS, 256>>>(x, Wqkv, (__half2*)xh_p, wq_p);

    // fused: qkv GEMM (+rope/pack/V) with Wout transpose hidden in extra blocks
    gemm_qkv<<<dim3(FQKV / 128, GQ_YB + GQ_EXTRA_Y), 256, GEMM_SMEM>>>(
        xh_p, wq_p, cosb, sinb, qp_p, kp_p, vt_p, Wout, wo_p);

    // attention -> yh
    {
        dim3 grid(T_SZ / 128, NH, B_SZ);
        attn_mma<<<grid, 256, ATTN_SMEM_BYTES>>>(qp_p, kp_p, vt_p, yh_p);
    }

    // out = y @ Wout  (big-tile GEMM, 128x256, 1 CTA/SM)
    gemm_big<<<dim3(DEMB / 256, M / 128), 256, BG_SMEM>>>(
        yh_p, wo_p, out, M, DEMB, DEMB);
}